// round 4
// baseline (speedup 1.0000x reference)
#include <cuda_runtime.h>
#include <math.h>

#define TXX 160
#define TYY 40
#define BB  16
#define HH  256
#define CC  512
#define INP 128
#define VV  30000
#define FD  (HH + CC + INP)   // 896

// ---------------- scratch (static __device__, allowed; 16B-aligned for float4 access) ----------------
__device__ __align__(16) float g_pctx[TXX * BB * CC];        // 5.24 MB
__device__ __align__(16) float g_ygates[TYY * BB * 4 * HH];  // 2.6 MB
__device__ __align__(16) float g_blstm[4 * HH];
__device__ __align__(16) float g_h[BB * HH];
__device__ __align__(16) float g_c[BB * HH];
__device__ __align__(16) float g_h1[BB * HH];
__device__ __align__(16) float g_c1[BB * HH];
__device__ __align__(16) float g_hq[BB * CC];
__device__ __align__(16) float g_sc[TXX * BB];
__device__ __align__(16) float g_acc[BB * TXX];
__device__ __align__(16) float g_atted[BB * CC];
__device__ __align__(16) float g_feats[TYY * BB * FD];       // 2.3 MB
__device__ __align__(16) float g_logits[TYY * BB * VV];      // 76.8 MB
__device__ __align__(16) float g_lse[TYY * BB];
__device__ __align__(16) float g_cost[TYY * BB];
__device__ __align__(16) float g_covpart[TYY * BB];

// ---------------- helpers ----------------
__device__ __forceinline__ float sigf(float x) { return 1.0f / (1.0f + expf(-x)); }

__device__ __forceinline__ unsigned long long ffma2(unsigned long long a, unsigned long long b, unsigned long long c) {
    unsigned long long r;
    asm("fma.rn.f32x2 %0,%1,%2,%3;" : "=l"(r) : "l"(a), "l"(b), "l"(c));
    return r;
}
__device__ __forceinline__ unsigned long long pack2(float x, float y) {
    unsigned long long r;
    asm("mov.b64 %0,{%1,%2};" : "=l"(r) : "f"(x), "f"(y));
    return r;
}
__device__ __forceinline__ float2 unpk2(unsigned long long v) {
    float2 f;
    asm("mov.b64 {%0,%1},%2;" : "=f"(f.x), "=f"(f.y) : "l"(v));
    return f;
}

// ---------------- generic tiled GEMM: C[M,N] = A[M,K] * B[N,K]^T + bias[N] ----------------
// BM=BN=128, BK=16, 256 threads, per-thread 8x8 via packed f32x2 (FFMA2 = 2x fp32 rate)
template<int M_, int N_, int K_>
__device__ __forceinline__ void gemm_body(const float* __restrict__ A, const float* __restrict__ B,
                                          const float* __restrict__ bias, float* __restrict__ C) {
    constexpr int BM = 128, BN = 128, BK = 16;
    __shared__ float As[BK][BM];
    __shared__ float Bs[BK][BN];
    int tid = threadIdx.x;
    int tm = tid >> 4;       // 0..15
    int tn = tid & 15;       // 0..15
    int m0 = blockIdx.y * BM;
    int n0 = blockIdx.x * BN;

    unsigned long long acc[4][8];
#pragma unroll
    for (int p = 0; p < 4; p++)
#pragma unroll
        for (int j = 0; j < 8; j++) acc[p][j] = 0ULL;

    for (int k0 = 0; k0 < K_; k0 += BK) {
#pragma unroll
        for (int i = 0; i < 2; i++) {
            int f4 = tid + i * 256;          // 0..511
            int r = f4 >> 2;                 // 0..127
            int kc = (f4 & 3) * 4;
            int gm = m0 + r;
            float4 v = make_float4(0.f, 0.f, 0.f, 0.f);
            if (gm < M_) v = *(const float4*)(A + (size_t)gm * K_ + k0 + kc);
            As[kc + 0][r] = v.x; As[kc + 1][r] = v.y; As[kc + 2][r] = v.z; As[kc + 3][r] = v.w;
        }
#pragma unroll
        for (int i = 0; i < 2; i++) {
            int f4 = tid + i * 256;
            int r = f4 >> 2;
            int kc = (f4 & 3) * 4;
            int gn = n0 + r;
            float4 v = make_float4(0.f, 0.f, 0.f, 0.f);
            if (gn < N_) v = *(const float4*)(B + (size_t)gn * K_ + k0 + kc);
            Bs[kc + 0][r] = v.x; Bs[kc + 1][r] = v.y; Bs[kc + 2][r] = v.z; Bs[kc + 3][r] = v.w;
        }
        __syncthreads();
#pragma unroll
        for (int k = 0; k < BK; k++) {
            unsigned long long a[4];
            const unsigned long long* Ap = (const unsigned long long*)&As[k][tm * 8];
            a[0] = Ap[0]; a[1] = Ap[1]; a[2] = Ap[2]; a[3] = Ap[3];
            const float4* Bp = (const float4*)&Bs[k][tn * 8];
            float4 b03 = Bp[0], b47 = Bp[1];
            unsigned long long bb[8];
            bb[0] = pack2(b03.x, b03.x); bb[1] = pack2(b03.y, b03.y);
            bb[2] = pack2(b03.z, b03.z); bb[3] = pack2(b03.w, b03.w);
            bb[4] = pack2(b47.x, b47.x); bb[5] = pack2(b47.y, b47.y);
            bb[6] = pack2(b47.z, b47.z); bb[7] = pack2(b47.w, b47.w);
#pragma unroll
            for (int p = 0; p < 4; p++)
#pragma unroll
                for (int j = 0; j < 8; j++) acc[p][j] = ffma2(a[p], bb[j], acc[p][j]);
        }
        __syncthreads();
    }
#pragma unroll
    for (int j = 0; j < 8; j++) {
        int gn = n0 + tn * 8 + j;
        if (gn >= N_) continue;
        float bv = bias[gn];
#pragma unroll
        for (int p = 0; p < 4; p++) {
            float2 v = unpk2(acc[p][j]);
            int gm = m0 + tm * 8 + 2 * p;
            if (gm < M_)     C[(size_t)gm * N_ + gn]       = v.x + bv;
            if (gm + 1 < M_) C[(size_t)(gm + 1) * N_ + gn] = v.y + bv;
        }
    }
}

__global__ void __launch_bounds__(256) gemm_pctx_k(const float* __restrict__ ctx, const float* __restrict__ W,
                                                   const float* __restrict__ bias) {
    gemm_body<TXX * BB, CC, CC>(ctx, W, bias, g_pctx);
}
__global__ void __launch_bounds__(256) gemm_ygates_k(const float* __restrict__ ye, const float* __restrict__ W) {
    gemm_body<TYY * BB, 4 * HH, INP>(ye, W, g_blstm, g_ygates);
}
__global__ void __launch_bounds__(256) gemm_logits_k(const float* __restrict__ Wp, const float* __restrict__ bp) {
    gemm_body<TYY * BB, VV, FD>(g_feats, Wp, bp, g_logits);
}

// ---------------- init: h/c/acc/b_lstm and the y_emb slice of feats ----------------
__global__ void __launch_bounds__(256) k_init(const float* __restrict__ h0, const float* __restrict__ c0,
                                              const float* __restrict__ initcov,
                                              const float* __restrict__ bih, const float* __restrict__ bhh,
                                              const float* __restrict__ yemb) {
    int i = blockIdx.x * 256 + threadIdx.x;
    if (i < BB * HH) { g_h[i] = h0[i]; g_c[i] = c0[i]; }
    if (i < BB * TXX) g_acc[i] = initcov[i];
    if (i < 4 * HH) g_blstm[i] = bih[i] + bhh[i];
    if (i < TYY * BB * INP) {
        int r = i / INP, cc2 = i - r * INP;
        g_feats[(size_t)r * FD + HH + CC + cc2] = yemb[i];
    }
}

// ---------------- step stage 1: gates -> h1,c1 ----------------
// one warp per (b,j): 4 dot-products of length H against W_hh rows
__global__ void __launch_bounds__(256) k_gates(const float* __restrict__ Whh, const float* __restrict__ ymask, int t) {
    int unit = blockIdx.x * 8 + (threadIdx.x >> 5);  // 0..4095
    int lane = threadIdx.x & 31;
    int b = unit >> 8, j = unit & 255;
    const float* hrow = g_h + b * HH;
    float s0 = 0.f, s1 = 0.f, s2 = 0.f, s3 = 0.f;
    for (int k = lane; k < HH; k += 32) {
        float hv = hrow[k];
        s0 += Whh[(0 * HH + j) * HH + k] * hv;
        s1 += Whh[(1 * HH + j) * HH + k] * hv;
        s2 += Whh[(2 * HH + j) * HH + k] * hv;
        s3 += Whh[(3 * HH + j) * HH + k] * hv;
    }
#pragma unroll
    for (int o = 16; o; o >>= 1) {
        s0 += __shfl_down_sync(0xFFFFFFFFu, s0, o);
        s1 += __shfl_down_sync(0xFFFFFFFFu, s1, o);
        s2 += __shfl_down_sync(0xFFFFFFFFu, s2, o);
        s3 += __shfl_down_sync(0xFFFFFFFFu, s3, o);
    }
    if (lane == 0) {
        const float* yg = g_ygates + (size_t)(t * BB + b) * (4 * HH);
        float gi = s0 + yg[j];
        float gf = s1 + yg[HH + j];
        float gg = s2 + yg[2 * HH + j];
        float go = s3 + yg[3 * HH + j];
        float co = g_c[b * HH + j], ho = g_h[b * HH + j];
        float c1 = sigf(gf) * co + sigf(gi) * tanhf(gg);
        float h1 = sigf(go) * tanhf(c1);
        float ym = ymask[t * BB + b];
        g_h1[b * HH + j] = ym * h1 + (1.f - ym) * ho;
        g_c1[b * HH + j] = ym * c1 + (1.f - ym) * co;
    }
}

// ---------------- step stage 2: hq = [h1,c1] @ W_comb_att.T ----------------
__global__ void __launch_bounds__(256) k_hq(const float* __restrict__ Wcomb) {
    int unit = blockIdx.x * 8 + (threadIdx.x >> 5);  // 0..8191
    int lane = threadIdx.x & 31;
    int b = unit >> 9, n = unit & 511;
    float s = 0.f;
    const float* wr = Wcomb + (size_t)n * (2 * HH);
    for (int k = lane; k < 2 * HH; k += 32) {
        float sv = (k < HH) ? g_h1[b * HH + k] : g_c1[b * HH + k - HH];
        s += wr[k] * sv;
    }
#pragma unroll
    for (int o = 16; o; o >>= 1) s += __shfl_down_sync(0xFFFFFFFFu, s, o);
    if (lane == 0) g_hq[b * CC + n] = s;
}

// ---------------- step stage 3: attention scores ----------------
__global__ void __launch_bounds__(256) k_scores(const float* __restrict__ xmask, const float* __restrict__ wcov,
                                                const float* __restrict__ uv) {
    int unit = blockIdx.x * 8 + (threadIdx.x >> 5);  // 0..2559
    int lane = threadIdx.x & 31;
    int tx = unit >> 4, b = unit & 15;
    float a = g_acc[b * TXX + tx];
    const float* prow = g_pctx + (size_t)(tx * BB + b) * CC;
    const float* qrow = g_hq + b * CC;
    float s = 0.f;
    for (int c = lane; c < CC; c += 32) {
        float v = prow[c] + qrow[c] + a * wcov[c];
        s += tanhf(v) * uv[c];
    }
#pragma unroll
    for (int o = 16; o; o >>= 1) s += __shfl_down_sync(0xFFFFFFFFu, s, o);
    if (lane == 0) g_sc[tx * BB + b] = xmask[tx * BB + b] * s;
}

// ---------------- step stage 4: softmax over TX, coverage, atted ----------------
__global__ void __launch_bounds__(512) k_att(const float* __restrict__ ctx, const float* __restrict__ xmask, int t) {
    int b = blockIdx.x, tid = threadIdx.x, lane = tid & 31, w = tid >> 5;
    __shared__ float sw[TXX];
    __shared__ float scr[16];
    __shared__ float sbc;
    float v = -3.0e38f;
    if (tid < TXX) { float s = g_sc[tid * BB + b]; sw[tid] = s; v = s; }
#pragma unroll
    for (int o = 16; o; o >>= 1) v = fmaxf(v, __shfl_down_sync(0xFFFFFFFFu, v, o));
    if (lane == 0) scr[w] = v;
    __syncthreads();
    if (tid == 0) { float m = scr[0]; for (int i = 1; i < 16; i++) m = fmaxf(m, scr[i]); sbc = m; }
    __syncthreads();
    float mx = sbc;
    float e = 0.f;
    if (tid < TXX) { e = expf(sw[tid] - mx) * xmask[tid * BB + b]; sw[tid] = e; }
    float s = e;
#pragma unroll
    for (int o = 16; o; o >>= 1) s += __shfl_down_sync(0xFFFFFFFFu, s, o);
    if (lane == 0) scr[w] = s;
    __syncthreads();
    if (tid == 0) { float m = 0.f; for (int i = 0; i < 16; i++) m += scr[i]; sbc = m; }
    __syncthreads();
    float inv = 1.f / sbc;
    float cterm = 0.f;
    if (tid < TXX) {
        float wn = sw[tid] * inv;
        sw[tid] = wn;
        float ao = g_acc[b * TXX + tid];
        cterm = fminf(wn, ao);
        g_acc[b * TXX + tid] = ao + wn;
    }
    __syncthreads();
    float cs = cterm;
#pragma unroll
    for (int o = 16; o; o >>= 1) cs += __shfl_down_sync(0xFFFFFFFFu, cs, o);
    if (lane == 0) scr[w] = cs;
    __syncthreads();
    if (tid == 0) { float m = 0.f; for (int i = 0; i < 16; i++) m += scr[i]; g_covpart[t * BB + b] = m; }
    if (tid < CC) {
        float a = 0.f;
#pragma unroll 8
        for (int tx = 0; tx < TXX; tx++) a += sw[tx] * ctx[(size_t)(tx * BB + b) * CC + tid];
        g_atted[b * CC + tid] = a;
        g_feats[(size_t)(t * BB + b) * FD + HH + tid] = a;
    }
}

// ---------------- step stage 5: second cell -> h2,c2, feats ----------------
__global__ void __launch_bounds__(256) k_ifoc(const float* __restrict__ Ux, const float* __restrict__ Wx,
                                              const float* __restrict__ bx, const float* __restrict__ ymask, int t) {
    int unit = blockIdx.x * 8 + (threadIdx.x >> 5);  // 0..4095
    int lane = threadIdx.x & 31;
    int b = unit >> 8, j = unit & 255;
    const float* h1r = g_h1 + b * HH;
    const float* atr = g_atted + b * CC;
    float s0 = 0.f, s1 = 0.f, s2 = 0.f, s3 = 0.f;
    for (int k = lane; k < HH; k += 32) {
        float hv = h1r[k];
        s0 += Ux[(0 * HH + j) * HH + k] * hv;
        s1 += Ux[(1 * HH + j) * HH + k] * hv;
        s2 += Ux[(2 * HH + j) * HH + k] * hv;
        s3 += Ux[(3 * HH + j) * HH + k] * hv;
    }
    for (int k = lane; k < CC; k += 32) {
        float av = atr[k];
        s0 += Wx[(size_t)(0 * HH + j) * CC + k] * av;
        s1 += Wx[(size_t)(1 * HH + j) * CC + k] * av;
        s2 += Wx[(size_t)(2 * HH + j) * CC + k] * av;
        s3 += Wx[(size_t)(3 * HH + j) * CC + k] * av;
    }
#pragma unroll
    for (int o = 16; o; o >>= 1) {
        s0 += __shfl_down_sync(0xFFFFFFFFu, s0, o);
        s1 += __shfl_down_sync(0xFFFFFFFFu, s1, o);
        s2 += __shfl_down_sync(0xFFFFFFFFu, s2, o);
        s3 += __shfl_down_sync(0xFFFFFFFFu, s3, o);
    }
    if (lane == 0) {
        float i2 = s0 + bx[j];
        float f2 = s1 + bx[HH + j];
        float o2 = s2 + bx[2 * HH + j];
        float g2 = s3 + bx[3 * HH + j];
        float c1v = g_c1[b * HH + j], h1v = g_h1[b * HH + j];
        float c2 = sigf(f2) * c1v + sigf(i2) * tanhf(g2);
        float h2 = sigf(o2) * tanhf(c2);
        float ym = ymask[t * BB + b];
        c2 = ym * c2 + (1.f - ym) * c1v;
        h2 = ym * h2 + (1.f - ym) * h1v;
        g_c[b * HH + j] = c2;
        g_h[b * HH + j] = h2;
        g_feats[(size_t)(t * BB + b) * FD + j] = h2;
    }
}

// ---------------- logsumexp + NLL cost per (t,b) row ----------------
__global__ void __launch_bounds__(256) k_lse(const int* __restrict__ yidx) {
    int row = blockIdx.x, tid = threadIdx.x, lane = tid & 31, w = tid >> 5;
    const float* lp = g_logits + (size_t)row * VV;
    __shared__ float scr[8];
    __shared__ float sbc;
    float mx = -3.0e38f;
    for (int i = tid; i < VV; i += 256) mx = fmaxf(mx, lp[i]);
#pragma unroll
    for (int o = 16; o; o >>= 1) mx = fmaxf(mx, __shfl_down_sync(0xFFFFFFFFu, mx, o));
    if (lane == 0) scr[w] = mx;
    __syncthreads();
    if (tid == 0) { float m = scr[0]; for (int i = 1; i < 8; i++) m = fmaxf(m, scr[i]); sbc = m; }
    __syncthreads();
    float m = sbc;
    float s = 0.f;
    for (int i = tid; i < VV; i += 256) s += expf(lp[i] - m);
#pragma unroll
    for (int o = 16; o; o >>= 1) s += __shfl_down_sync(0xFFFFFFFFu, s, o);
    if (lane == 0) scr[w] = s;
    __syncthreads();
    if (tid == 0) {
        float tot = 0.f;
        for (int i = 0; i < 8; i++) tot += scr[i];
        float lse = m + logf(tot);
        g_lse[row] = lse;
        g_cost[row] = lse - lp[yidx[row]];
    }
}

// ---------------- final softmax of last-step logits into out ----------------
__global__ void __launch_bounds__(256) k_ypred(float* __restrict__ out) {
    int i = blockIdx.x * 256 + threadIdx.x;
    if (i < BB * VV) {
        int b = i / VV;
        int v = i - b * VV;
        int row = (TYY - 1) * BB + b;
        out[i] = expf(g_logits[(size_t)row * VV + v] - g_lse[row]);
    }
}

// ---------------- two scalar outputs ----------------
__global__ void __launch_bounds__(256) k_scalars(const float* __restrict__ ymask, float* __restrict__ out) {
    int tid = threadIdx.x, lane = tid & 31, w = tid >> 5;
    __shared__ float sb[BB];
    __shared__ float scr[8];
    if (tid < BB) {
        float num = 0.f, den = 0.f;
        for (int t = 0; t < TYY; t++) {
            float ym = ymask[t * BB + tid];
            num += g_cost[t * BB + tid] * ym;
            den += ym;
        }
        sb[tid] = num / den;
    }
    __syncthreads();
    if (tid == 0) {
        float s = 0.f;
        for (int b = 0; b < BB; b++) s += sb[b];
        out[BB * VV] = s / (float)BB;
    }
    float cv = 0.f;
    for (int i = tid; i < TYY * BB; i += 256) cv += g_covpart[i];
#pragma unroll
    for (int o = 16; o; o >>= 1) cv += __shfl_down_sync(0xFFFFFFFFu, cv, o);
    if (lane == 0) scr[w] = cv;
    __syncthreads();
    if (tid == 0) {
        float tot = 0.f;
        for (int i = 0; i < 8; i++) tot += scr[i];
        out[BB * VV + 1] = tot / (float)(TYY * BB);
    }
}

// ---------------- host ----------------
extern "C" void kernel_launch(void* const* d_in, const int* in_sizes, int n_in,
                              void* d_out, int out_size) {
    const float* y_emb    = (const float*)d_in[0];
    const float* context  = (const float*)d_in[1];
    const float* h0       = (const float*)d_in[2];
    const float* c0       = (const float*)d_in[3];
    const float* x_mask   = (const float*)d_in[4];
    const float* y_mask   = (const float*)d_in[5];
    const float* init_cov = (const float*)d_in[6];
    const int*   y_idx    = (const int*)  d_in[7];
    const float* W_ih     = (const float*)d_in[8];
    const float* W_hh     = (const float*)d_in[9];
    const float* b_ih     = (const float*)d_in[10];
    const float* b_hh     = (const float*)d_in[11];
    const float* Wx       = (const float*)d_in[12];
    const float* Ux       = (const float*)d_in[13];
    const float* bx       = (const float*)d_in[14];
    const float* Wc_att   = (const float*)d_in[15];
    const float* b_att    = (const float*)d_in[16];
    const float* W_comb   = (const float*)d_in[17];
    const float* U_att    = (const float*)d_in[18];
    const float* W_cov    = (const float*)d_in[19];
    const float* Wp       = (const float*)d_in[20];
    const float* bp       = (const float*)d_in[21];
    float* out = (float*)d_out;

    // init state + b_lstm + y_emb slice of feats
    k_init<<<(TYY * BB * INP + 255) / 256, 256>>>(h0, c0, init_cov, b_ih, b_hh, y_emb);

    // pctx = context @ Wc_att.T + b_att   (M=2560,N=512,K=512)
    gemm_pctx_k<<<dim3(CC / 128, (TXX * BB) / 128), 256>>>(context, Wc_att, b_att);
    // ygates = y_emb @ W_ih.T + b_lstm    (M=640,N=1024,K=128)
    gemm_ygates_k<<<dim3((4 * HH) / 128, (TYY * BB) / 128), 256>>>(y_emb, W_ih);

    // sequential recurrence: 5 stages per step
    for (int t = 0; t < TYY; t++) {
        k_gates <<<512, 256>>>(W_hh, y_mask, t);
        k_hq    <<<1024, 256>>>(W_comb);
        k_scores<<<320, 256>>>(x_mask, W_cov, U_att);
        k_att   <<<BB, 512>>>(context, x_mask, t);
        k_ifoc  <<<512, 256>>>(Ux, Wx, bx, y_mask, t);
    }

    // logits = feats @ Wp.T + bp   (M=640,N=30000,K=896)
    gemm_logits_k<<<dim3((VV + 127) / 128, (TYY * BB) / 128), 256>>>(Wp, bp);

    // per-row logsumexp + target cost
    k_lse<<<TYY * BB, 256>>>(y_idx);

    // outputs
    k_ypred<<<(BB * VV + 255) / 256, 256>>>(out);
    k_scalars<<<1, 256>>>(y_mask, out);
}